// round 15
// baseline (speedup 1.0000x reference)
#include <cuda_runtime.h>
#include <cstdint>

// Problem constants
#define B_DIM 512
#define IN_F  512
#define OUT_F 512
#define NOISE 128
#define WCOLS (OUT_F * NOISE)   // 65536 : columns of Wmat = (o,n)
#define TAIL  (IN_F * OUT_F)    // 262144 : start of bias rows in hyper_W / hyper_b

typedef unsigned long long ull;

// ---- packed f32x2 helpers (SASS FFMA2 path, sm_100+) ----
__device__ __forceinline__ ull dup_f32(float a) {
    ull r; asm("mov.b64 %0, {%1, %1};" : "=l"(r) : "f"(a)); return r;
}
__device__ __forceinline__ void fma2(ull &c, ull a, ull b) {
    asm("fma.rn.f32x2 %0, %1, %2, %0;" : "+l"(c) : "l"(a), "l"(b));
}
__device__ __forceinline__ float2 unpack_f32x2(ull v) {
    float2 r; asm("mov.b64 {%0, %1}, %2;" : "=f"(r.x), "=f"(r.y) : "l"(v)); return r;
}

// ============================================================================
// Kernel 1: out[b,o] = hb_tail[o] + pb_tail[o]   (initializes poisoned d_out)
// ============================================================================
__global__ void init_tail_kernel(const float* __restrict__ hb,
                                 const float* __restrict__ pb,
                                 float* __restrict__ out) {
    const int o = threadIdx.x;        // 512 threads
    const int b = blockIdx.x;         // 512 blocks
    out[b * OUT_F + o] = hb[TAIL + o] + pb[TAIL + o];
}

// ============================================================================
// Kernel 2: out += x @ Hb + prior_x @ Pb
//   Hb[i][o] = hb[i*OUT_F + o]  (and same for pb). Small: 268 M-MAC total.
//   Grid (8,8,4): 64x64 tiles, z = K-split (z<2: x/hb halves, z>=2: px/pb).
// ============================================================================
__global__ __launch_bounds__(256)
void bias_gemm_kernel(const float* __restrict__ x, const float* __restrict__ px,
                      const float* __restrict__ hb, const float* __restrict__ pb,
                      float* __restrict__ out) {
    __shared__ float As2[16][68];
    __shared__ float Bs2[16][68];

    const int tid = threadIdx.x;
    const int tx = tid & 15, ty = tid >> 4;
    const int b0 = blockIdx.x * 64;
    const int o0 = blockIdx.y * 64;
    const int z  = blockIdx.z;

    const float* Asrc = (z >= 2) ? px : x;
    const float* Bsrc = (z >= 2) ? pb : hb;
    const int kbase = (z & 1) * 256;

    const int bA = tid >> 2, qA = (tid & 3) * 4;   // A loader: row bA, 4 k's
    const int kB = tid >> 4, oB = (tid & 15) * 4;  // B loader: row kB, 4 o's

    float c[4][4] = {};
    for (int kt = 0; kt < 16; ++kt) {
        const int k0 = kbase + kt * 16;
        float4 a = *(const float4*)(Asrc + (b0 + bA) * IN_F + k0 + qA);
        float4 b = *(const float4*)(Bsrc + (k0 + kB) * OUT_F + o0 + oB);
        __syncthreads();
        As2[qA + 0][bA] = a.x; As2[qA + 1][bA] = a.y;
        As2[qA + 2][bA] = a.z; As2[qA + 3][bA] = a.w;
        *(float4*)&Bs2[kB][oB] = b;
        __syncthreads();
        #pragma unroll
        for (int kk = 0; kk < 16; ++kk) {
            float4 fa = *(const float4*)&As2[kk][ty * 4];
            float4 fb = *(const float4*)&Bs2[kk][tx * 4];
            float av[4] = {fa.x, fa.y, fa.z, fa.w};
            float bv[4] = {fb.x, fb.y, fb.z, fb.w};
            #pragma unroll
            for (int r = 0; r < 4; ++r)
                #pragma unroll
                for (int j = 0; j < 4; ++j) c[r][j] += av[r] * bv[j];
        }
    }
    #pragma unroll
    for (int r = 0; r < 4; ++r)
        #pragma unroll
        for (int j = 0; j < 4; ++j)
            atomicAdd(out + (b0 + ty * 4 + r) * OUT_F + (o0 + tx * 4 + j), c[r][j]);
}

// ============================================================================
// Kernel 3 (main): fused G-GEMM + noise contraction + tail-weight fold.
//   Per CTA: 128(b) x 128(n, one o) tile of G = X(128x512) @ Wmat(512x128),
//   K = 512 in 32 double-buffered ktiles of 16, 8x8 per thread via f32x2 FMA.
//   Epilogue: out[b,o] += sum_n (G[b,n] + Wtail[o,n]) * noise[b,n]  (atomic).
//   Grid (4, 512, 2): btile fastest-varying -> the 4 CTAs sharing a W column
//   block run in the same wave -> W read once from HBM (L2 dedup).
// ============================================================================
__global__ __launch_bounds__(256, 2)
void main_gemm_kernel(const float* __restrict__ x, const float* __restrict__ px,
                      const float* __restrict__ noise,
                      const float* __restrict__ hW, const float* __restrict__ pW,
                      float* __restrict__ out) {
    __shared__ float As[2][16][132];   // As[k][b] (transposed x tile), padded
    __shared__ float Bs[2][16][132];   // Bs[k][n] (natural W tile), padded
    __shared__ float sred[128 * 17];   // epilogue cross-tx reduction

    const int tid = threadIdx.x;
    const int tx = tid & 15, ty = tid >> 4;
    const int b0   = blockIdx.x * 128;
    const int o    = blockIdx.y;
    const int path = blockIdx.z;

    const float* Ap = path ? px : x;
    const float* Wp = path ? pW : hW;
    const int ocol = o * NOISE;

    // loader thread mapping
    const int bA = tid >> 1, hA = (tid & 1) * 8;    // A: row bA, k offset hA (+0..7)
    const int kB = tid >> 4, nB = (tid & 15) * 8;   // B: row kB, col nB (+0..7)

    const float* agp = Ap + (b0 + bA) * IN_F + hA;
    const float* bgp = Wp + kB * WCOLS + ocol + nB;

    ull acc[8][4];
    #pragma unroll
    for (int r = 0; r < 8; ++r)
        #pragma unroll
        for (int j = 0; j < 4; ++j) acc[r][j] = 0ull;

    // initial tile (kt = 0) -> buffer 0
    {
        float4 a0 = *(const float4*)(agp);
        float4 a1 = *(const float4*)(agp + 4);
        float4 w0 = *(const float4*)(bgp);
        float4 w1 = *(const float4*)(bgp + 4);
        float av[8] = {a0.x, a0.y, a0.z, a0.w, a1.x, a1.y, a1.z, a1.w};
        #pragma unroll
        for (int j = 0; j < 8; ++j) As[0][hA + j][bA] = av[j];
        *(float4*)&Bs[0][kB][nB]     = w0;
        *(float4*)&Bs[0][kB][nB + 4] = w1;
    }
    __syncthreads();

    #pragma unroll 1
    for (int kt = 0; kt < 32; ++kt) {
        const int cur = kt & 1;
        float4 a0, a1, w0, w1;
        if (kt < 31) {   // prefetch next ktile into registers
            const int k0n = (kt + 1) * 16;
            a0 = *(const float4*)(agp + k0n);
            a1 = *(const float4*)(agp + k0n + 4);
            w0 = *(const float4*)(bgp + k0n * WCOLS);
            w1 = *(const float4*)(bgp + k0n * WCOLS + 4);
        }
        #pragma unroll
        for (int kk = 0; kk < 16; ++kk) {
            float4 fa0 = *(const float4*)&As[cur][kk][ty * 8];
            float4 fa1 = *(const float4*)&As[cur][kk][ty * 8 + 4];
            const ull* bp = (const ull*)&Bs[cur][kk][tx * 8];
            ull bv0 = bp[0], bv1 = bp[1], bv2 = bp[2], bv3 = bp[3];
            float av[8] = {fa0.x, fa0.y, fa0.z, fa0.w, fa1.x, fa1.y, fa1.z, fa1.w};
            #pragma unroll
            for (int r = 0; r < 8; ++r) {
                ull aa = dup_f32(av[r]);
                fma2(acc[r][0], aa, bv0);
                fma2(acc[r][1], aa, bv1);
                fma2(acc[r][2], aa, bv2);
                fma2(acc[r][3], aa, bv3);
            }
        }
        if (kt < 31) {   // stage prefetched tile into the other buffer
            const int nb = cur ^ 1;
            float av[8] = {a0.x, a0.y, a0.z, a0.w, a1.x, a1.y, a1.z, a1.w};
            #pragma unroll
            for (int j = 0; j < 8; ++j) As[nb][hA + j][bA] = av[j];
            *(float4*)&Bs[nb][kB][nB]     = w0;
            *(float4*)&Bs[nb][kB][nB + 4] = w1;
        }
        __syncthreads();
    }

    // ---- epilogue: fold tail weights, contract n with noise, reduce, atomic ----
    const float* wt = Wp + (TAIL + o) * NOISE + tx * 8;   // hW_tail[o, n-slice]
    float4 t0 = *(const float4*)(wt);
    float4 t1 = *(const float4*)(wt + 4);
    float wv[8] = {t0.x, t0.y, t0.z, t0.w, t1.x, t1.y, t1.z, t1.w};

    #pragma unroll
    for (int r = 0; r < 8; ++r) {
        const int brow = b0 + ty * 8 + r;
        const float* np = noise + brow * NOISE + tx * 8;
        float4 n0 = *(const float4*)(np);
        float4 n1 = *(const float4*)(np + 4);
        float nv[8] = {n0.x, n0.y, n0.z, n0.w, n1.x, n1.y, n1.z, n1.w};
        float s = 0.f;
        #pragma unroll
        for (int j = 0; j < 4; ++j) {
            float2 c = unpack_f32x2(acc[r][j]);
            s += (c.x + wv[2 * j])     * nv[2 * j];
            s += (c.y + wv[2 * j + 1]) * nv[2 * j + 1];
        }
        sred[(ty * 8 + r) * 17 + tx] = s;
    }
    __syncthreads();
    if (tid < 128) {
        float v = 0.f;
        #pragma unroll
        for (int t = 0; t < 16; ++t) v += sred[tid * 17 + t];
        atomicAdd(out + (b0 + tid) * OUT_F + o, v);
    }
}

// ============================================================================
// Inputs (metadata order): x, prior_x, hyper_noise, hyper_W, hyper_b,
//                          prior_W, prior_b.  Output: (512, 512) fp32.
// ============================================================================
extern "C" void kernel_launch(void* const* d_in, const int* in_sizes, int n_in,
                              void* d_out, int out_size) {
    const float* x  = (const float*)d_in[0];
    const float* px = (const float*)d_in[1];
    const float* nz = (const float*)d_in[2];
    const float* hW = (const float*)d_in[3];
    const float* hb = (const float*)d_in[4];
    const float* pW = (const float*)d_in[5];
    const float* pb = (const float*)d_in[6];
    float* out = (float*)d_out;

    // Sequential on one stream: init -> bias GEMM (atomic) -> main (atomic).
    init_tail_kernel<<<512, 512>>>(hb, pb, out);
    bias_gemm_kernel<<<dim3(8, 8, 4), 256>>>(x, px, hb, pb, out);
    main_gemm_kernel<<<dim3(4, 512, 2), 256>>>(x, px, nz, hW, pW, out);
}

// round 16
// speedup vs baseline: 2.1223x; 2.1223x over previous
#include <cuda_runtime.h>
#include <cuda_bf16.h>
#include <cstdint>

// Problem constants
#define B_DIM 512
#define IN_F  512
#define OUT_F 512
#define NOISE 128
#define WCOLS (OUT_F * NOISE)   // 65536 : columns of Wmat = (o,n)
#define TAIL  (IN_F * OUT_F)    // 262144 : start of bias rows in hyper_W / hyper_b

// ============================================================================
// Kernel 1: out[b,o] = hb_tail[o] + pb_tail[o]   (initializes poisoned d_out)
// ============================================================================
__global__ void init_tail_kernel(const float* __restrict__ hb,
                                 const float* __restrict__ pb,
                                 float* __restrict__ out) {
    const int o = threadIdx.x;
    const int b = blockIdx.x;
    out[b * OUT_F + o] = hb[TAIL + o] + pb[TAIL + o];
}

// ============================================================================
// Kernel 2: out += x @ Hb + prior_x @ Pb   (bias-row GEMM, 268 M-MAC, fp32)
// ============================================================================
__global__ __launch_bounds__(256)
void bias_gemm_kernel(const float* __restrict__ x, const float* __restrict__ px,
                      const float* __restrict__ hb, const float* __restrict__ pb,
                      float* __restrict__ out) {
    __shared__ float As2[16][68];
    __shared__ float Bs2[16][68];

    const int tid = threadIdx.x;
    const int tx = tid & 15, ty = tid >> 4;
    const int b0 = blockIdx.x * 64;
    const int o0 = blockIdx.y * 64;
    const int z  = blockIdx.z;

    const float* Asrc = (z >= 2) ? px : x;
    const float* Bsrc = (z >= 2) ? pb : hb;
    const int kbase = (z & 1) * 256;

    const int bA = tid >> 2, qA = (tid & 3) * 4;
    const int kB = tid >> 4, oB = (tid & 15) * 4;

    float c[4][4] = {};
    for (int kt = 0; kt < 16; ++kt) {
        const int k0 = kbase + kt * 16;
        float4 a = *(const float4*)(Asrc + (b0 + bA) * IN_F + k0 + qA);
        float4 b = *(const float4*)(Bsrc + (k0 + kB) * OUT_F + o0 + oB);
        __syncthreads();
        As2[qA + 0][bA] = a.x; As2[qA + 1][bA] = a.y;
        As2[qA + 2][bA] = a.z; As2[qA + 3][bA] = a.w;
        *(float4*)&Bs2[kB][oB] = b;
        __syncthreads();
        #pragma unroll
        for (int kk = 0; kk < 16; ++kk) {
            float4 fa = *(const float4*)&As2[kk][ty * 4];
            float4 fb = *(const float4*)&Bs2[kk][tx * 4];
            float av[4] = {fa.x, fa.y, fa.z, fa.w};
            float bv[4] = {fb.x, fb.y, fb.z, fb.w};
            #pragma unroll
            for (int r = 0; r < 4; ++r)
                #pragma unroll
                for (int j = 0; j < 4; ++j) c[r][j] += av[r] * bv[j];
        }
    }
    #pragma unroll
    for (int r = 0; r < 4; ++r)
        #pragma unroll
        for (int j = 0; j < 4; ++j)
            atomicAdd(out + (b0 + ty * 4 + r) * OUT_F + (o0 + tx * 4 + j), c[r][j]);
}

// ============================================================================
// Kernel 3 (main): bf16 3-split tensor-core G-GEMM + fused noise contraction.
//   Per CTA: 128(b) x 128(n, one o), K=512 in 16 double-buffered ktiles of 32.
//   fp32 tiles are loaded to regs, split into bf16 hi/lo, staged in smem;
//   compute = mma.sync.m16n8k16: Ahi*Bhi + Ahi*Blo + Alo*Bhi (fp32 accum).
//   Epilogue: out[b,o] += sum_n (G[b,n] + Wtail[o,n]) * noise[b,n]  (atomic).
// ============================================================================
#define APITCH 40     // halves per A smem row (80B pitch: conflict-free ldmatrix)
#define BPITCH 136    // halves per B smem row (272B pitch: conflict-free trans)
#define AS_SPLIT 5120 // 128 * 40 halves per (buf,split)
#define BS_SPLIT 4352 // 32 * 136 halves per (buf,split)
#define SMEM_AS_BYTES (4 * AS_SPLIT * 2)           // 40960
#define SMEM_BS_BYTES (4 * BS_SPLIT * 2)           // 34816
#define SMEM_SRED_OFF (SMEM_AS_BYTES + SMEM_BS_BYTES)
#define SMEM_TOTAL (SMEM_SRED_OFF + 128 * 5 * 4)   // 78336

#define MMA_OP(c, a, b) asm volatile( \
    "mma.sync.aligned.m16n8k16.row.col.f32.bf16.bf16.f32 " \
    "{%0,%1,%2,%3}, {%4,%5,%6,%7}, {%8,%9}, {%0,%1,%2,%3};" \
    : "+f"((c)[0]), "+f"((c)[1]), "+f"((c)[2]), "+f"((c)[3]) \
    : "r"((a)[0]), "r"((a)[1]), "r"((a)[2]), "r"((a)[3]), \
      "r"((b)[0]), "r"((b)[1]))

#define LDSM_X4(r, addr) asm volatile( \
    "ldmatrix.sync.aligned.m8n8.x4.shared.b16 {%0,%1,%2,%3}, [%4];" \
    : "=r"((r)[0]), "=r"((r)[1]), "=r"((r)[2]), "=r"((r)[3]) : "r"(addr))

#define LDSM_X2T(r, addr) asm volatile( \
    "ldmatrix.sync.aligned.m8n8.x2.trans.shared.b16 {%0,%1}, [%2];" \
    : "=r"((r)[0]), "=r"((r)[1]) : "r"(addr))

// split 4 fp32 into bf16 hi/lo pairs, store 8B each to hi/lo smem locations
__device__ __forceinline__ void split_store(float a, float b, float c, float d,
                                            __nv_bfloat16* hi_p,
                                            __nv_bfloat16* lo_p) {
    __nv_bfloat162 h0 = __floats2bfloat162_rn(a, b);
    __nv_bfloat162 h1 = __floats2bfloat162_rn(c, d);
    float2 f0 = __bfloat1622float2(h0);
    float2 f1 = __bfloat1622float2(h1);
    __nv_bfloat162 l0 = __floats2bfloat162_rn(a - f0.x, b - f0.y);
    __nv_bfloat162 l1 = __floats2bfloat162_rn(c - f1.x, d - f1.y);
    uint2 hv, lv;
    hv.x = *(unsigned*)&h0; hv.y = *(unsigned*)&h1;
    lv.x = *(unsigned*)&l0; lv.y = *(unsigned*)&l1;
    *(uint2*)hi_p = hv;
    *(uint2*)lo_p = lv;
}

__global__ __launch_bounds__(256, 1)
void main_mma_kernel(const float* __restrict__ x, const float* __restrict__ px,
                     const float* __restrict__ noise,
                     const float* __restrict__ hW, const float* __restrict__ pW,
                     float* __restrict__ out) {
    extern __shared__ char smem_raw[];
    __nv_bfloat16* As = (__nv_bfloat16*)smem_raw;                   // [buf*2+split][128*APITCH]
    __nv_bfloat16* Bs = (__nv_bfloat16*)(smem_raw + SMEM_AS_BYTES); // [buf*2+split][32*BPITCH]
    float* sred = (float*)(smem_raw + SMEM_SRED_OFF);               // [128][5]

    const unsigned as_base = (unsigned)__cvta_generic_to_shared(As);
    const unsigned bs_base = (unsigned)__cvta_generic_to_shared(Bs);

    const int tid  = threadIdx.x;
    const int lane = tid & 31;
    const int w    = tid >> 5;
    const int wm   = w >> 2;      // 0..1 : m-group (64 rows)
    const int wn   = w & 3;       // 0..3 : n-group (32 cols)

    const int b0   = blockIdx.x * 128;
    const int o    = blockIdx.y;
    const int path = blockIdx.z;
    const float* Ap = path ? px : x;
    const float* Wp = path ? pW : hW;

    // loader mapping (every thread loads both A and B pieces)
    const int arow = tid >> 1;            // 0..127
    const int acol = (tid & 1) * 16;      // 0 / 16
    const int brow = tid >> 3;            // 0..31
    const int bcol = (tid & 7) * 16;      // 0..112

    const float* agp0 = Ap + (size_t)(b0 + arow) * IN_F + acol;
    const float* bgp0 = Wp + (size_t)brow * WCOLS + (size_t)o * NOISE + bcol;

    float acc[4][4][4];   // [mi][ni][r] fp32 accumulators (64 regs)
    #pragma unroll
    for (int mi = 0; mi < 4; ++mi)
        #pragma unroll
        for (int ni = 0; ni < 4; ++ni)
            #pragma unroll
            for (int r = 0; r < 4; ++r) acc[mi][ni][r] = 0.f;

    float4 pf[8];   // prefetch regs: pf[0..3] = A, pf[4..7] = B

    // ---- initial tile (kt = 0) ----
    #pragma unroll
    for (int i = 0; i < 4; ++i) pf[i]     = *(const float4*)(agp0 + i * 4);
    #pragma unroll
    for (int i = 0; i < 4; ++i) pf[4 + i] = *(const float4*)(bgp0 + i * 4);
    #pragma unroll
    for (int i = 0; i < 4; ++i) {
        int col = acol + i * 4;
        split_store(pf[i].x, pf[i].y, pf[i].z, pf[i].w,
                    As + 0 * AS_SPLIT + arow * APITCH + col,
                    As + 1 * AS_SPLIT + arow * APITCH + col);
    }
    #pragma unroll
    for (int i = 0; i < 4; ++i) {
        int col = bcol + i * 4;
        split_store(pf[4 + i].x, pf[4 + i].y, pf[4 + i].z, pf[4 + i].w,
                    Bs + 0 * BS_SPLIT + brow * BPITCH + col,
                    Bs + 1 * BS_SPLIT + brow * BPITCH + col);
    }
    __syncthreads();

    #pragma unroll 1
    for (int kt = 0; kt < 16; ++kt) {
        const int cur = kt & 1;

        if (kt < 15) {   // prefetch next ktile (fp32) into registers
            const float* ag = agp0 + (kt + 1) * 32;
            const float* bg = bgp0 + (size_t)(kt + 1) * 32 * WCOLS;
            #pragma unroll
            for (int i = 0; i < 4; ++i) pf[i]     = *(const float4*)(ag + i * 4);
            #pragma unroll
            for (int i = 0; i < 4; ++i) pf[4 + i] = *(const float4*)(bg + i * 4);
        }

        // ---- compute on buffer `cur`: two k16 steps ----
        #pragma unroll
        for (int s16 = 0; s16 < 2; ++s16) {
            const int k0 = s16 * 16;
            unsigned af[4][2][4];   // [mi][split][reg]
            unsigned bfr[4][2][2];  // [ni][split][reg]
            #pragma unroll
            for (int mi = 0; mi < 4; ++mi)
                #pragma unroll
                for (int s = 0; s < 2; ++s) {
                    int row = wm * 64 + mi * 16 + (lane & 15);
                    int col = k0 + (lane >> 4) * 8;
                    unsigned addr = as_base +
                        ((cur * 2 + s) * AS_SPLIT + row * APITCH + col) * 2;
                    LDSM_X4(af[mi][s], addr);
                }
            #pragma unroll
            for (int ni = 0; ni < 4; ++ni)
                #pragma unroll
                for (int s = 0; s < 2; ++s) {
                    int row = k0 + (lane & 15);
                    int col = wn * 32 + ni * 8;
                    unsigned addr = bs_base +
                        ((cur * 2 + s) * BS_SPLIT + row * BPITCH + col) * 2;
                    LDSM_X2T(bfr[ni][s], addr);
                }
            #pragma unroll
            for (int mi = 0; mi < 4; ++mi)
                #pragma unroll
                for (int ni = 0; ni < 4; ++ni) {
                    MMA_OP(acc[mi][ni], af[mi][0], bfr[ni][0]);  // hi*hi
                    MMA_OP(acc[mi][ni], af[mi][0], bfr[ni][1]);  // hi*lo
                    MMA_OP(acc[mi][ni], af[mi][1], bfr[ni][0]);  // lo*hi
                }
        }

        if (kt < 15) {   // stage prefetched tile into the other buffer
            const int nb = cur ^ 1;
            #pragma unroll
            for (int i = 0; i < 4; ++i) {
                int col = acol + i * 4;
                split_store(pf[i].x, pf[i].y, pf[i].z, pf[i].w,
                            As + (nb * 2 + 0) * AS_SPLIT + arow * APITCH + col,
                            As + (nb * 2 + 1) * AS_SPLIT + arow * APITCH + col);
            }
            #pragma unroll
            for (int i = 0; i < 4; ++i) {
                int col = bcol + i * 4;
                split_store(pf[4 + i].x, pf[4 + i].y, pf[4 + i].z, pf[4 + i].w,
                            Bs + (nb * 2 + 0) * BS_SPLIT + brow * BPITCH + col,
                            Bs + (nb * 2 + 1) * BS_SPLIT + brow * BPITCH + col);
            }
        }
        __syncthreads();
    }

    // ---- epilogue: (G + Wtail[o,n]) * noise[b,n], reduce over n, atomic ----
    const size_t wtoff = (size_t)(TAIL + o) * NOISE + wn * 32 + (lane & 3) * 2;
    float2 wtv[4];
    #pragma unroll
    for (int ni = 0; ni < 4; ++ni)
        wtv[ni] = *(const float2*)(Wp + wtoff + ni * 8);

    #pragma unroll
    for (int mi = 0; mi < 4; ++mi) {
        #pragma unroll
        for (int rh = 0; rh < 2; ++rh) {
            int row = wm * 64 + mi * 16 + (lane >> 2) + rh * 8;
            const float* np = noise + (size_t)(b0 + row) * NOISE +
                              wn * 32 + (lane & 3) * 2;
            float s = 0.f;
            #pragma unroll
            for (int ni = 0; ni < 4; ++ni) {
                float2 nv = *(const float2*)(np + ni * 8);
                s += (acc[mi][ni][rh * 2 + 0] + wtv[ni].x) * nv.x;
                s += (acc[mi][ni][rh * 2 + 1] + wtv[ni].y) * nv.y;
            }
            s += __shfl_xor_sync(0xffffffffu, s, 1);
            s += __shfl_xor_sync(0xffffffffu, s, 2);
            if ((lane & 3) == 0) sred[row * 5 + wn] = s;
        }
    }
    __syncthreads();
    if (tid < 128) {
        float v = sred[tid * 5 + 0] + sred[tid * 5 + 1] +
                  sred[tid * 5 + 2] + sred[tid * 5 + 3];
        atomicAdd(out + (size_t)(b0 + tid) * OUT_F + o, v);
    }
}

// ============================================================================
// Inputs (metadata order): x, prior_x, hyper_noise, hyper_W, hyper_b,
//                          prior_W, prior_b.  Output: (512, 512) fp32.
// ============================================================================
extern "C" void kernel_launch(void* const* d_in, const int* in_sizes, int n_in,
                              void* d_out, int out_size) {
    const float* x  = (const float*)d_in[0];
    const float* px = (const float*)d_in[1];
    const float* nz = (const float*)d_in[2];
    const float* hW = (const float*)d_in[3];
    const float* hb = (const float*)d_in[4];
    const float* pW = (const float*)d_in[5];
    const float* pb = (const float*)d_in[6];
    float* out = (float*)d_out;

    cudaFuncSetAttribute(main_mma_kernel,
                         cudaFuncAttributeMaxDynamicSharedMemorySize, SMEM_TOTAL);

    init_tail_kernel<<<512, 512>>>(hb, pb, out);
    bias_gemm_kernel<<<dim3(8, 8, 4), 256>>>(x, px, hb, pb, out);
    main_mma_kernel<<<dim3(4, 512, 2), 256, SMEM_TOTAL>>>(x, px, nz, hW, pW, out);
}